// round 1
// baseline (speedup 1.0000x reference)
#include <cuda_runtime.h>

#define BB 256
#define TT 25
#define PRE 2048
#define DD 256
#define FOURD 1024
#define K2D 2048

// ---------------- scratch (device globals; no allocations allowed) ----------
__device__ float g_x[2][BB * TT * DD];   // frontend outputs xv/xt
__device__ float g_h[2][BB * DD];        // h_v, h_t
__device__ float g_c[2][BB * DD];        // c_v, c_t
__device__ float g_zz[BB * DD];          // z feedback
__device__ float g_s[2][BB * FOURD];     // LSTHM pre-activations
__device__ float g_att[BB * K2D];        // attention logits -> softmax in place
__device__ float g_r[2][BB * DD];        // rv, rt

struct KP {
    const float *p0, *p1, *p2, *p3, *p4, *p5, *p6, *p7;
    int t;
};

enum { M_FRONT = 0, M_LSTHM, M_ATT, M_RED, M_MABOUT };

template <int MODE> __host__ __device__ constexpr int kdim() {
    return MODE == M_FRONT ? 2048 : MODE == M_LSTHM ? 768
         : MODE == M_ATT   ? 512  : MODE == M_RED   ? 1024 : 512;
}

// ---- A-tile loader: W consecutive floats at (row m, col k) -----------------
template <int MODE, int W>
__device__ __forceinline__ void loadA(const KP& p, int m, int k, int s, float* o) {
    if constexpr (MODE == M_RED) {
        // fused attend: A[m,k] = att[m, slot*512 + s*256 + d] * h_s[m, d]
        int slot = k >> 8, d = k & 255;
        const float* a = g_att + m * K2D + slot * 512 + s * DD + d;
        const float* h = g_h[s] + m * DD + d;
        if constexpr (W == 4) {
            float4 av = *(const float4*)a; float4 hv = *(const float4*)h;
            o[0] = av.x * hv.x; o[1] = av.y * hv.y; o[2] = av.z * hv.z; o[3] = av.w * hv.w;
        } else {
            float2 av = *(const float2*)a; float2 hv = *(const float2*)h;
            o[0] = av.x * hv.x; o[1] = av.y * hv.y;
        }
        return;
    }
    const float* src = nullptr;
    if constexpr (MODE == M_FRONT) {
        src = (s ? p.p1 : p.p0) + (size_t)m * PRE + k;
    } else if constexpr (MODE == M_LSTHM) {
        if (k < DD)            src = g_x[s] + (m * TT + p.t) * DD + k;
        else if (k < 2 * DD)   src = g_h[s] + m * DD + (k - DD);
        else                   src = g_zz   + m * DD + (k - 2 * DD);
    } else if constexpr (MODE == M_ATT) {
        src = (k < DD) ? g_h[0] + m * DD + k : g_h[1] + m * DD + (k - DD);
    } else { // M_MABOUT
        src = (k < DD) ? g_r[0] + m * DD + k : g_r[1] + m * DD + (k - DD);
    }
    if constexpr (W == 4) {
        float4 v = *(const float4*)src; o[0] = v.x; o[1] = v.y; o[2] = v.z; o[3] = v.w;
    } else {
        float2 v = *(const float2*)src; o[0] = v.x; o[1] = v.y;
    }
}

// ---- B-tile (weight) loader: W consecutive floats at (row k, col n) --------
template <int MODE, int W>
__device__ __forceinline__ void loadB(const KP& p, int k, int n, int s, float* o) {
    const float* src;
    if constexpr (MODE == M_FRONT) {
        src = (s ? p.p3 : p.p2) + (size_t)k * 256 + n;
    } else if constexpr (MODE == M_LSTHM) {
        const float* base;
        if (k < DD)           base = s ? p.p3 : p.p0;  // W
        else if (k < 2 * DD)  base = s ? p.p4 : p.p1;  // U
        else                  base = s ? p.p5 : p.p2;  // V
        src = base + (k & 255) * FOURD + n;
    } else if constexpr (MODE == M_ATT) {
        src = p.p0 + (size_t)k * K2D + n;
    } else if constexpr (MODE == M_RED) {
        src = (s ? p.p1 : p.p0) + (size_t)k * 256 + n;
    } else { // M_MABOUT
        src = p.p0 + (size_t)k * 256 + n;
    }
    if constexpr (W == 4) {
        float4 v = *(const float4*)src; o[0] = v.x; o[1] = v.y; o[2] = v.z; o[3] = v.w;
    } else {
        float2 v = *(const float2*)src; o[0] = v.x; o[1] = v.y;
    }
}

template <int MODE>
__device__ __forceinline__ const float* biasp(const KP& p, int s) {
    if constexpr (MODE == M_FRONT)  return s ? p.p5 : p.p4;
    else if constexpr (MODE == M_LSTHM) return s ? p.p7 : p.p6;
    else if constexpr (MODE == M_ATT)   return p.p4;
    else if constexpr (MODE == M_RED)   return s ? p.p5 : p.p4;
    else return p.p4;
}

template <int MODE>
__device__ __forceinline__ void storeC(int m, int n, int s, float v) {
    if constexpr (MODE == M_FRONT)       g_x[s][m * DD + n] = v;
    else if constexpr (MODE == M_LSTHM)  g_s[s][m * FOURD + n] = v;
    else if constexpr (MODE == M_ATT)    g_att[m * K2D + n] = v;
    else if constexpr (MODE == M_RED)    g_r[s][m * DD + n] = fmaxf(v, 0.0f);
    else                                 g_zz[m * DD + n] = v;
}

// ---------------- generic tiled fp32 GEMM kernel ----------------------------
template <int MODE, int BM, int BN, int TM, int TN>
__global__ __launch_bounds__(256) void gk(KP p) {
    constexpr int KD = kdim<MODE>();
    constexpr int NTX = BN / TN;
    static_assert((BM / TM) * (BN / TN) == 256, "256 threads");
    constexpr int AW = (BM * 16) / 256;  // floats/thread for A tile (4 or 2)
    constexpr int BW = (BN * 16) / 256;  // floats/thread for B tile (4 or 2)

    const int s  = blockIdx.z;
    const int m0 = blockIdx.y * BM, n0 = blockIdx.x * BN;
    const int tid = threadIdx.x;
    const int tx = tid % NTX, ty = tid / NTX;

    __shared__ float As[16 * (BM + 1)];  // As[k][m], padded stride
    __shared__ float Bs[16 * BN];        // Bs[k][n]

    float acc[TM][TN];
#pragma unroll
    for (int i = 0; i < TM; i++)
#pragma unroll
        for (int j = 0; j < TN; j++) acc[i][j] = 0.0f;

    for (int k0 = 0; k0 < KD; k0 += 16) {
        {
            constexpr int TPRA = 16 / AW;
            int r = tid / TPRA;
            int c = (tid % TPRA) * AW;
            float tmp[AW];
            loadA<MODE, AW>(p, m0 + r, k0 + c, s, tmp);
#pragma unroll
            for (int w = 0; w < AW; w++) As[(c + w) * (BM + 1) + r] = tmp[w];
        }
        {
            int r = tid >> 4;
            int c = (tid & 15) * BW;
            float tmp[BW];
            loadB<MODE, BW>(p, k0 + r, n0 + c, s, tmp);
#pragma unroll
            for (int w = 0; w < BW; w++) Bs[r * BN + c + w] = tmp[w];
        }
        __syncthreads();
#pragma unroll
        for (int kk = 0; kk < 16; kk++) {
            float ar[TM], br[TN];
#pragma unroll
            for (int i = 0; i < TM; i++) ar[i] = As[kk * (BM + 1) + ty * TM + i];
#pragma unroll
            for (int j = 0; j < TN; j++) br[j] = Bs[kk * BN + tx * TN + j];
#pragma unroll
            for (int i = 0; i < TM; i++)
#pragma unroll
                for (int j = 0; j < TN; j++)
                    acc[i][j] = fmaf(ar[i], br[j], acc[i][j]);
        }
        __syncthreads();
    }

    const float* bp = biasp<MODE>(p, s);
#pragma unroll
    for (int i = 0; i < TM; i++)
#pragma unroll
        for (int j = 0; j < TN; j++) {
            int m = m0 + ty * TM + i, n = n0 + tx * TN + j;
            storeC<MODE>(m, n, s, acc[i][j] + bp[n]);
        }
}

// ---------------- elementwise / small kernels -------------------------------
__global__ void k_init() {
    int idx = blockIdx.x * 256 + threadIdx.x;  // BB*DD threads
    g_h[0][idx] = 0.f; g_h[1][idx] = 0.f;
    g_c[0][idx] = 0.f; g_c[1][idx] = 0.f;
    g_zz[idx] = 0.f;
}

__global__ void k_gates() {
    int idx = blockIdx.x * 256 + threadIdx.x;  // 2*BB*DD
    int s = idx >> 16;          // BB*DD = 65536
    int r = idx & 65535;
    int b = r >> 8, d = r & 255;
    const float* sv = g_s[s] + b * FOURD;
    float f  = 1.0f / (1.0f + expf(-sv[d]));
    float i  = 1.0f / (1.0f + expf(-sv[DD + d]));
    float o  = 1.0f / (1.0f + expf(-sv[2 * DD + d]));
    float ch = tanhf(sv[3 * DD + d]);
    float c  = f * g_c[s][r] + i * ch;
    g_c[s][r] = c;
    g_h[s][r] = tanhf(c) * o;
}

__global__ void k_softmax() {
    int b = blockIdx.x, tid = threadIdx.x;
    float* row = g_att + b * K2D;
    float v[8];
    float lmax = -1e30f;
#pragma unroll
    for (int i = 0; i < 8; i++) { v[i] = row[tid + 256 * i]; lmax = fmaxf(lmax, v[i]); }
    __shared__ float s1[8], s2[8];
    int lane = tid & 31, w = tid >> 5;
#pragma unroll
    for (int o = 16; o; o >>= 1) lmax = fmaxf(lmax, __shfl_xor_sync(0xffffffffu, lmax, o));
    if (lane == 0) s1[w] = lmax;
    __syncthreads();
    float gmax = fmaxf(fmaxf(fmaxf(s1[0], s1[1]), fmaxf(s1[2], s1[3])),
                       fmaxf(fmaxf(s1[4], s1[5]), fmaxf(s1[6], s1[7])));
    float lsum = 0.0f;
#pragma unroll
    for (int i = 0; i < 8; i++) { v[i] = expf(v[i] - gmax); lsum += v[i]; }
#pragma unroll
    for (int o = 16; o; o >>= 1) lsum += __shfl_xor_sync(0xffffffffu, lsum, o);
    if (lane == 0) s2[w] = lsum;
    __syncthreads();
    float gsum = s2[0] + s2[1] + s2[2] + s2[3] + s2[4] + s2[5] + s2[6] + s2[7];
    float inv = 1.0f / gsum;
#pragma unroll
    for (int i = 0; i < 8; i++) row[tid + 256 * i] = v[i] * inv;
}

__global__ void k_final(const float* __restrict__ w0, const float* __restrict__ b0,
                        const float* __restrict__ w1, const float* __restrict__ b1,
                        float* __restrict__ out) {
    int b = blockIdx.x, tid = threadIdx.x;
    __shared__ float hrow[512];
    __shared__ float red[256];
    hrow[tid]       = g_h[0][b * DD + tid];
    hrow[256 + tid] = g_h[1][b * DD + tid];
    __syncthreads();
    float acc = b0[tid];
#pragma unroll 8
    for (int k = 0; k < 512; k++) acc = fmaf(hrow[k], w0[k * DD + tid], acc);
    float w1a = w1[tid * 2 + 0], w1b = w1[tid * 2 + 1];

    red[tid] = acc * w1a;
    __syncthreads();
    for (int st = 128; st; st >>= 1) { if (tid < st) red[tid] += red[tid + st]; __syncthreads(); }
    if (tid == 0) out[b * 2 + 0] = red[0] + b1[0];
    __syncthreads();
    red[tid] = acc * w1b;
    __syncthreads();
    for (int st = 128; st; st >>= 1) { if (tid < st) red[tid] += red[tid + st]; __syncthreads(); }
    if (tid == 0) out[b * 2 + 1] = red[0] + b1[1];
}

// ---------------- launch ----------------------------------------------------
extern "C" void kernel_launch(void* const* d_in, const int* in_sizes, int n_in,
                              void* d_out, int out_size) {
    const float* xv       = (const float*)d_in[0];
    const float* xt       = (const float*)d_in[1];
    const float* fc0_w    = (const float*)d_in[2];
    const float* fc0_b    = (const float*)d_in[3];
    const float* fc1_w    = (const float*)d_in[4];
    const float* fc1_b    = (const float*)d_in[5];
    const float* lvW      = (const float*)d_in[6];
    const float* lvU      = (const float*)d_in[7];
    const float* lvV      = (const float*)d_in[8];
    const float* lvb      = (const float*)d_in[9];
    const float* ltW      = (const float*)d_in[10];
    const float* ltU      = (const float*)d_in[11];
    const float* ltV      = (const float*)d_in[12];
    const float* ltb      = (const float*)d_in[13];
    const float* att_w    = (const float*)d_in[14];
    const float* att_b    = (const float*)d_in[15];
    const float* red_v_w  = (const float*)d_in[16];
    const float* red_v_b  = (const float*)d_in[17];
    const float* red_t_w  = (const float*)d_in[18];
    const float* red_t_b  = (const float*)d_in[19];
    const float* mab_w    = (const float*)d_in[20];
    const float* mab_b    = (const float*)d_in[21];
    const float* late0_w  = (const float*)d_in[22];
    const float* late0_b  = (const float*)d_in[23];
    const float* late1_w  = (const float*)d_in[24];
    const float* late1_b  = (const float*)d_in[25];
    float* out = (float*)d_out;

    k_init<<<BB * DD / 256, 256>>>();

    KP pf{xv, xt, fc0_w, fc1_w, fc0_b, fc1_b, nullptr, nullptr, 0};
    gk<M_FRONT, 64, 64, 4, 4><<<dim3(4, 100, 2), 256>>>(pf);

    KP pl{lvW, lvU, lvV, ltW, ltU, ltV, lvb, ltb, 0};
    KP pa{att_w, nullptr, nullptr, nullptr, att_b, nullptr, nullptr, nullptr, 0};
    KP pr{red_v_w, red_t_w, nullptr, nullptr, red_v_b, red_t_b, nullptr, nullptr, 0};
    KP pm{mab_w, nullptr, nullptr, nullptr, mab_b, nullptr, nullptr, nullptr, 0};

    for (int t = 0; t < TT; t++) {
        pl.t = t;
        gk<M_LSTHM, 32, 64, 2, 4><<<dim3(16, 8, 2), 256>>>(pl);   // s pre-acts
        k_gates<<<512, 256>>>();                                   // c,h update
        gk<M_ATT, 32, 64, 2, 4><<<dim3(32, 8, 1), 256>>>(pa);      // logits
        k_softmax<<<BB, 256>>>();                                  // softmax 2048
        gk<M_RED, 32, 32, 2, 2><<<dim3(8, 8, 2), 256>>>(pr);       // fused attend+reduce+relu
        gk<M_MABOUT, 32, 32, 2, 2><<<dim3(8, 8, 1), 256>>>(pm);    // zz
    }

    k_final<<<BB, 256>>>(late0_w, late0_b, late1_w, late1_b, out);
}

// round 2
// speedup vs baseline: 1.5472x; 1.5472x over previous
#include <cuda_runtime.h>
#include <cstdint>

#define BB 256
#define TT 25
#define PRE 2048
#define DD 256
#define FOURD 1024
#define K2D 2048

// ---------------- scratch (device globals; no allocations allowed) ----------
__device__ float g_x[2][BB * TT * DD];   // frontend outputs xv/xt
__device__ float g_h[2][BB * DD];        // h_v, h_t
__device__ float g_c[2][BB * DD];        // c_v, c_t
__device__ float g_zz[BB * DD];          // z feedback
__device__ float g_s[2][BB * FOURD];     // LSTHM pre-activations
__device__ float g_att[BB * K2D];        // attention logits -> softmax in place
__device__ float g_r[2][BB * DD];        // rv, rt

struct KP {
    const float *p0, *p1, *p2, *p3, *p4, *p5, *p6, *p7;
    int t;
};

enum { M_FRONT = 0, M_LSTHM, M_ATT, M_RED, M_MABOUT };

template <int MODE> __host__ __device__ constexpr int kdim() {
    return MODE == M_FRONT ? 2048 : MODE == M_LSTHM ? 768
         : MODE == M_ATT   ? 512  : MODE == M_RED   ? 1024 : 512;
}

// ---- A-tile loader: W consecutive floats at (row m, col k) -----------------
template <int MODE, int W>
__device__ __forceinline__ void loadA(const KP& p, int m, int k, int s, float* o) {
    if constexpr (MODE == M_RED) {
        // fused attend: A[m,k] = att[m, slot*512 + s*256 + d] * h_s[m, d]
        int slot = k >> 8, d = k & 255;
        const float* a = g_att + m * K2D + slot * 512 + s * DD + d;
        const float* h = g_h[s] + m * DD + d;
        if constexpr (W == 4) {
            float4 av = *(const float4*)a; float4 hv = *(const float4*)h;
            o[0] = av.x * hv.x; o[1] = av.y * hv.y; o[2] = av.z * hv.z; o[3] = av.w * hv.w;
        } else {
            float2 av = *(const float2*)a; float2 hv = *(const float2*)h;
            o[0] = av.x * hv.x; o[1] = av.y * hv.y;
        }
        return;
    }
    const float* src = nullptr;
    if constexpr (MODE == M_FRONT) {
        src = (s ? p.p1 : p.p0) + (size_t)m * PRE + k;
    } else if constexpr (MODE == M_LSTHM) {
        if (k < DD)            src = g_x[s] + (m * TT + p.t) * DD + k;
        else if (k < 2 * DD)   src = g_h[s] + m * DD + (k - DD);
        else                   src = g_zz   + m * DD + (k - 2 * DD);
    } else if constexpr (MODE == M_ATT) {
        src = (k < DD) ? g_h[0] + m * DD + k : g_h[1] + m * DD + (k - DD);
    } else { // M_MABOUT
        src = (k < DD) ? g_r[0] + m * DD + k : g_r[1] + m * DD + (k - DD);
    }
    if constexpr (W == 4) {
        float4 v = *(const float4*)src; o[0] = v.x; o[1] = v.y; o[2] = v.z; o[3] = v.w;
    } else {
        float2 v = *(const float2*)src; o[0] = v.x; o[1] = v.y;
    }
}

// ---- B-tile (weight) loader: W consecutive floats at (row k, col n) --------
template <int MODE, int W>
__device__ __forceinline__ void loadB(const KP& p, int k, int n, int s, float* o) {
    const float* src;
    if constexpr (MODE == M_FRONT) {
        src = (s ? p.p3 : p.p2) + (size_t)k * 256 + n;
    } else if constexpr (MODE == M_LSTHM) {
        const float* base;
        if (k < DD)           base = s ? p.p3 : p.p0;  // W
        else if (k < 2 * DD)  base = s ? p.p4 : p.p1;  // U
        else                  base = s ? p.p5 : p.p2;  // V
        src = base + (k & 255) * FOURD + n;
    } else if constexpr (MODE == M_ATT) {
        src = p.p0 + (size_t)k * K2D + n;
    } else if constexpr (MODE == M_RED) {
        src = (s ? p.p1 : p.p0) + (size_t)k * 256 + n;
    } else { // M_MABOUT
        src = p.p0 + (size_t)k * 256 + n;
    }
    if constexpr (W == 4) {
        float4 v = *(const float4*)src; o[0] = v.x; o[1] = v.y; o[2] = v.z; o[3] = v.w;
    } else {
        float2 v = *(const float2*)src; o[0] = v.x; o[1] = v.y;
    }
}

template <int MODE>
__device__ __forceinline__ const float* biasp(const KP& p, int s) {
    if constexpr (MODE == M_FRONT)  return s ? p.p5 : p.p4;
    else if constexpr (MODE == M_LSTHM) return s ? p.p7 : p.p6;
    else if constexpr (MODE == M_ATT)   return p.p4;
    else if constexpr (MODE == M_RED)   return s ? p.p5 : p.p4;
    else return p.p4;
}

template <int MODE>
__device__ __forceinline__ void storeC(int m, int n, int s, float v) {
    if constexpr (MODE == M_FRONT)       g_x[s][m * DD + n] = v;
    else if constexpr (MODE == M_LSTHM)  g_s[s][m * FOURD + n] = v;
    else if constexpr (MODE == M_ATT)    g_att[m * K2D + n] = v;
    else if constexpr (MODE == M_RED)    g_r[s][m * DD + n] = fmaxf(v, 0.0f);
    else                                 g_zz[m * DD + n] = v;
}

// ---- tf32 helpers -----------------------------------------------------------
__device__ __forceinline__ float to_tf32(float x) {
    asm("cvt.rna.tf32.f32 %0, %0;" : "+f"(x));
    return x;
}

__device__ __forceinline__ void mma_tf32(float* acc, const float* a, const float* b) {
    asm volatile(
        "mma.sync.aligned.m16n8k8.row.col.f32.tf32.tf32.f32 "
        "{%0,%1,%2,%3}, {%4,%5,%6,%7}, {%8,%9}, {%0,%1,%2,%3};\n"
        : "+f"(acc[0]), "+f"(acc[1]), "+f"(acc[2]), "+f"(acc[3])
        : "r"(__float_as_uint(a[0])), "r"(__float_as_uint(a[1])),
          "r"(__float_as_uint(a[2])), "r"(__float_as_uint(a[3])),
          "r"(__float_as_uint(b[0])), "r"(__float_as_uint(b[1])));
}

// ---------------- generic tiled tf32-MMA GEMM kernel ------------------------
// 256 threads = 8 warps, warp grid 2 (m) x 4 (n).
template <int MODE, int BM, int BN>
__global__ __launch_bounds__(256) void gk(KP p) {
    constexpr int KD = kdim<MODE>();
    constexpr int KT = 16;
    constexpr int WM = BM / 2;            // warp tile m
    constexpr int WN = BN / 4;            // warp tile n
    constexpr int MT = WM / 16;           // mma tiles per warp (m)
    constexpr int NT = WN / 8;            // mma tiles per warp (n)
    constexpr int SA = BM + 8;            // As row stride (bank-conflict-free frags)
    constexpr int SB = BN + 8;            // Bs row stride
    constexpr int AW = (BM * KT) / 256;   // floats/thread for A tile
    constexpr int BW = (BN * KT) / 256;   // floats/thread for B tile
    static_assert(MT >= 1 && NT >= 1, "tile");

    const int s  = blockIdx.z;
    const int m0 = blockIdx.y * BM, n0 = blockIdx.x * BN;
    const int tid = threadIdx.x;
    const int lane = tid & 31, wid = tid >> 5;
    const int wm = (wid & 1) * WM;        // warp m offset in block
    const int wn = (wid >> 1) * WN;       // warp n offset in block
    const int grp = lane >> 2, thr = lane & 3;

    __shared__ float As[KT * SA];         // As[k][m] (tf32 values)
    __shared__ float Bs[KT * SB];         // Bs[k][n] (tf32 values)

    float acc[MT][NT][4];
#pragma unroll
    for (int i = 0; i < MT; i++)
#pragma unroll
        for (int j = 0; j < NT; j++)
#pragma unroll
            for (int e = 0; e < 4; e++) acc[i][j][e] = 0.0f;

    for (int k0 = 0; k0 < KD; k0 += KT) {
        {
            constexpr int TPRA = KT / AW;
            int r = tid / TPRA;                 // m within tile
            int c = (tid % TPRA) * AW;          // k within tile
            float tmp[AW];
            loadA<MODE, AW>(p, m0 + r, k0 + c, s, tmp);
#pragma unroll
            for (int w = 0; w < AW; w++) As[(c + w) * SA + r] = to_tf32(tmp[w]);
        }
        {
            int r = tid >> 4;                   // k within tile
            int c = (tid & 15) * BW;            // n within tile
            float tmp[BW];
            loadB<MODE, BW>(p, k0 + r, n0 + c, s, tmp);
#pragma unroll
            for (int w = 0; w < BW; w++) Bs[r * SB + c + w] = to_tf32(tmp[w]);
        }
        __syncthreads();
#pragma unroll
        for (int kk = 0; kk < KT; kk += 8) {
            float afr[MT][4], bfr[NT][2];
#pragma unroll
            for (int mt = 0; mt < MT; mt++) {
                int mb = wm + mt * 16;
                afr[mt][0] = As[(kk + thr) * SA + mb + grp];
                afr[mt][1] = As[(kk + thr) * SA + mb + grp + 8];
                afr[mt][2] = As[(kk + thr + 4) * SA + mb + grp];
                afr[mt][3] = As[(kk + thr + 4) * SA + mb + grp + 8];
            }
#pragma unroll
            for (int nt = 0; nt < NT; nt++) {
                int nb = wn + nt * 8;
                bfr[nt][0] = Bs[(kk + thr) * SB + nb + grp];
                bfr[nt][1] = Bs[(kk + thr + 4) * SB + nb + grp];
            }
#pragma unroll
            for (int mt = 0; mt < MT; mt++)
#pragma unroll
                for (int nt = 0; nt < NT; nt++)
                    mma_tf32(acc[mt][nt], afr[mt], bfr[nt]);
        }
        __syncthreads();
    }

    const float* bp = biasp<MODE>(p, s);
#pragma unroll
    for (int mt = 0; mt < MT; mt++)
#pragma unroll
        for (int nt = 0; nt < NT; nt++)
#pragma unroll
            for (int e = 0; e < 4; e++) {
                int m = m0 + wm + mt * 16 + grp + ((e >= 2) ? 8 : 0);
                int n = n0 + wn + nt * 8 + 2 * thr + (e & 1);
                storeC<MODE>(m, n, s, acc[mt][nt][e] + bp[n]);
            }
}

// ---------------- elementwise / small kernels -------------------------------
__global__ void k_init() {
    int idx = blockIdx.x * 256 + threadIdx.x;  // BB*DD threads
    g_h[0][idx] = 0.f; g_h[1][idx] = 0.f;
    g_c[0][idx] = 0.f; g_c[1][idx] = 0.f;
    g_zz[idx] = 0.f;
}

__global__ void k_gates() {
    int idx = blockIdx.x * 256 + threadIdx.x;  // 2*BB*DD
    int s = idx >> 16;          // BB*DD = 65536
    int r = idx & 65535;
    int b = r >> 8, d = r & 255;
    const float* sv = g_s[s] + b * FOURD;
    float f  = 1.0f / (1.0f + expf(-sv[d]));
    float i  = 1.0f / (1.0f + expf(-sv[DD + d]));
    float o  = 1.0f / (1.0f + expf(-sv[2 * DD + d]));
    float ch = tanhf(sv[3 * DD + d]);
    float c  = f * g_c[s][r] + i * ch;
    g_c[s][r] = c;
    g_h[s][r] = tanhf(c) * o;
}

__global__ void k_softmax() {
    int b = blockIdx.x, tid = threadIdx.x;
    float* row = g_att + b * K2D;
    float v[8];
    float lmax = -1e30f;
#pragma unroll
    for (int i = 0; i < 8; i++) { v[i] = row[tid + 256 * i]; lmax = fmaxf(lmax, v[i]); }
    __shared__ float s1[8], s2[8];
    int lane = tid & 31, w = tid >> 5;
#pragma unroll
    for (int o = 16; o; o >>= 1) lmax = fmaxf(lmax, __shfl_xor_sync(0xffffffffu, lmax, o));
    if (lane == 0) s1[w] = lmax;
    __syncthreads();
    float gmax = fmaxf(fmaxf(fmaxf(s1[0], s1[1]), fmaxf(s1[2], s1[3])),
                       fmaxf(fmaxf(s1[4], s1[5]), fmaxf(s1[6], s1[7])));
    float lsum = 0.0f;
#pragma unroll
    for (int i = 0; i < 8; i++) { v[i] = expf(v[i] - gmax); lsum += v[i]; }
#pragma unroll
    for (int o = 16; o; o >>= 1) lsum += __shfl_xor_sync(0xffffffffu, lsum, o);
    if (lane == 0) s2[w] = lsum;
    __syncthreads();
    float gsum = s2[0] + s2[1] + s2[2] + s2[3] + s2[4] + s2[5] + s2[6] + s2[7];
    float inv = 1.0f / gsum;
#pragma unroll
    for (int i = 0; i < 8; i++) row[tid + 256 * i] = v[i] * inv;
}

__global__ void k_final(const float* __restrict__ w0, const float* __restrict__ b0,
                        const float* __restrict__ w1, const float* __restrict__ b1,
                        float* __restrict__ out) {
    int b = blockIdx.x, tid = threadIdx.x;
    __shared__ float hrow[512];
    __shared__ float red[256];
    hrow[tid]       = g_h[0][b * DD + tid];
    hrow[256 + tid] = g_h[1][b * DD + tid];
    __syncthreads();
    float acc = b0[tid];
#pragma unroll 8
    for (int k = 0; k < 512; k++) acc = fmaf(hrow[k], w0[k * DD + tid], acc);
    float w1a = w1[tid * 2 + 0], w1b = w1[tid * 2 + 1];

    red[tid] = acc * w1a;
    __syncthreads();
    for (int st = 128; st; st >>= 1) { if (tid < st) red[tid] += red[tid + st]; __syncthreads(); }
    if (tid == 0) out[b * 2 + 0] = red[0] + b1[0];
    __syncthreads();
    red[tid] = acc * w1b;
    __syncthreads();
    for (int st = 128; st; st >>= 1) { if (tid < st) red[tid] += red[tid + st]; __syncthreads(); }
    if (tid == 0) out[b * 2 + 1] = red[0] + b1[1];
}

// ---------------- launch ----------------------------------------------------
extern "C" void kernel_launch(void* const* d_in, const int* in_sizes, int n_in,
                              void* d_out, int out_size) {
    const float* xv       = (const float*)d_in[0];
    const float* xt       = (const float*)d_in[1];
    const float* fc0_w    = (const float*)d_in[2];
    const float* fc0_b    = (const float*)d_in[3];
    const float* fc1_w    = (const float*)d_in[4];
    const float* fc1_b    = (const float*)d_in[5];
    const float* lvW      = (const float*)d_in[6];
    const float* lvU      = (const float*)d_in[7];
    const float* lvV      = (const float*)d_in[8];
    const float* lvb      = (const float*)d_in[9];
    const float* ltW      = (const float*)d_in[10];
    const float* ltU      = (const float*)d_in[11];
    const float* ltV      = (const float*)d_in[12];
    const float* ltb      = (const float*)d_in[13];
    const float* att_w    = (const float*)d_in[14];
    const float* att_b    = (const float*)d_in[15];
    const float* red_v_w  = (const float*)d_in[16];
    const float* red_v_b  = (const float*)d_in[17];
    const float* red_t_w  = (const float*)d_in[18];
    const float* red_t_b  = (const float*)d_in[19];
    const float* mab_w    = (const float*)d_in[20];
    const float* mab_b    = (const float*)d_in[21];
    const float* late0_w  = (const float*)d_in[22];
    const float* late0_b  = (const float*)d_in[23];
    const float* late1_w  = (const float*)d_in[24];
    const float* late1_b  = (const float*)d_in[25];
    float* out = (float*)d_out;

    k_init<<<BB * DD / 256, 256>>>();

    KP pf{xv, xt, fc0_w, fc1_w, fc0_b, fc1_b, nullptr, nullptr, 0};
    gk<M_FRONT, 64, 64><<<dim3(4, 100, 2), 256>>>(pf);

    KP pl{lvW, lvU, lvV, ltW, ltU, ltV, lvb, ltb, 0};
    KP pa{att_w, nullptr, nullptr, nullptr, att_b, nullptr, nullptr, nullptr, 0};
    KP pr{red_v_w, red_t_w, nullptr, nullptr, red_v_b, red_t_b, nullptr, nullptr, 0};
    KP pm{mab_w, nullptr, nullptr, nullptr, mab_b, nullptr, nullptr, nullptr, 0};

    for (int t = 0; t < TT; t++) {
        pl.t = t;
        gk<M_LSTHM, 64, 64><<<dim3(16, 4, 2), 256>>>(pl);   // s pre-acts
        k_gates<<<512, 256>>>();                             // c,h update
        gk<M_ATT, 64, 64><<<dim3(32, 4, 1), 256>>>(pa);      // logits
        k_softmax<<<BB, 256>>>();                            // softmax 2048
        gk<M_RED, 32, 32><<<dim3(8, 8, 2), 256>>>(pr);       // fused attend+reduce+relu
        gk<M_MABOUT, 32, 32><<<dim3(8, 8, 1), 256>>>(pm);    // zz
    }

    k_final<<<BB, 256>>>(late0_w, late0_b, late1_w, late1_b, out);
}

// round 4
// speedup vs baseline: 1.6384x; 1.0589x over previous
#include <cuda_runtime.h>
#include <cstdint>

#define BB 256
#define TT 25
#define PRE 2048
#define DD 256
#define FOURD 1024
#define K2D 2048
#define NBLK 128

// ---------------- scratch (device globals) ----------------------------------
__device__ float g_x[2][BB * TT * DD];
__device__ float g_h[2][BB * DD];
__device__ float g_c[2][BB * DD];
__device__ float g_zz[BB * DD];
__device__ float g_s[2][BB * FOURD];
__device__ float g_att[BB * K2D];
__device__ float g_r[2][BB * DD];

// two-level grid barrier state (self-resetting)
__device__ unsigned g_leaf[16 * 32];   // one counter per 128B line
__device__ unsigned g_root = 0;
__device__ unsigned g_gen = 0;

struct RP {
    const float *xv, *xt, *fc0_w, *fc0_b, *fc1_w, *fc1_b;
    const float *lvW, *lvU, *lvV, *lvb, *ltW, *ltU, *ltV, *ltb;
    const float *att_w, *att_b, *red_v_w, *red_v_b, *red_t_w, *red_t_b, *mab_w, *mab_b;
    const float *late0_w, *late0_b, *late1_w, *late1_b;
    float* out;
};

enum { M_FRONT = 0, M_LSTHM, M_ATT, M_RED, M_MABOUT };

template <int MODE> __host__ __device__ constexpr int kdim() {
    return MODE == M_FRONT ? 2048 : MODE == M_LSTHM ? 768
         : MODE == M_ATT   ? 512  : MODE == M_RED   ? 1024 : 512;
}

// ---------------- grid sync (two-level, L2-atomic) ---------------------------
__device__ __forceinline__ void gsync() {
    __threadfence();            // make this block's writes visible device-wide
    __syncthreads();
    if (threadIdx.x == 0) {
        unsigned gen = *(volatile unsigned*)&g_gen;
        unsigned li = (blockIdx.x & 15) * 32;
        if (atomicAdd(&g_leaf[li], 1u) == 7u) {        // 8 blocks per leaf
            g_leaf[li] = 0;
            __threadfence();
            if (atomicAdd(&g_root, 1u) == 15u) {       // 16 leaves
                g_root = 0;
                __threadfence();
                *(volatile unsigned*)&g_gen = gen + 1;
            } else {
                while (*(volatile unsigned*)&g_gen == gen) {}
            }
        } else {
            while (*(volatile unsigned*)&g_gen == gen) {}
        }
    }
    __syncthreads();
}

// ---------------- tf32 helpers ----------------------------------------------
__device__ __forceinline__ float to_tf32(float x) {
    asm("cvt.rna.tf32.f32 %0, %0;" : "+f"(x));
    return x;
}

__device__ __forceinline__ void mma_tf32(float* acc, const float* a, const float* b) {
    asm volatile(
        "mma.sync.aligned.m16n8k8.row.col.f32.tf32.tf32.f32 "
        "{%0,%1,%2,%3}, {%4,%5,%6,%7}, {%8,%9}, {%0,%1,%2,%3};\n"
        : "+f"(acc[0]), "+f"(acc[1]), "+f"(acc[2]), "+f"(acc[3])
        : "r"(__float_as_uint(a[0])), "r"(__float_as_uint(a[1])),
          "r"(__float_as_uint(a[2])), "r"(__float_as_uint(a[3])),
          "r"(__float_as_uint(b[0])), "r"(__float_as_uint(b[1])));
}

// ---------------- loaders ----------------------------------------------------
// Scratch written inside the persistent launch is loaded with __ldcg (L2,
// cross-SM coherent after threadfence); inputs/weights use normal (L1) loads.
template <int MODE, int W>
__device__ __forceinline__ void loadA(const RP& P, int m, int k, int s, int t, float* o) {
    if constexpr (MODE == M_RED) {
        int slot = k >> 8, d = k & 255;
        float2 av = __ldcg((const float2*)(g_att + m * K2D + slot * 512 + s * DD + d));
        float2 hv = __ldcg((const float2*)(g_h[s] + m * DD + d));
        o[0] = av.x * hv.x; o[1] = av.y * hv.y;
    } else if constexpr (MODE == M_FRONT) {
        float4 v = *(const float4*)((s ? P.xt : P.xv) + (size_t)m * PRE + k);
        o[0] = v.x; o[1] = v.y; o[2] = v.z; o[3] = v.w;
    } else if constexpr (MODE == M_LSTHM) {
        float4 v;
        if (k < DD)          v = *(const float4*)(g_x[s] + (m * TT + t) * DD + k);
        else if (k < 2 * DD) v = __ldcg((const float4*)(g_h[s] + m * DD + (k - DD)));
        else                 v = __ldcg((const float4*)(g_zz + m * DD + (k - 2 * DD)));
        o[0] = v.x; o[1] = v.y; o[2] = v.z; o[3] = v.w;
    } else if constexpr (MODE == M_ATT) {
        const float* src = (k < DD) ? g_h[0] + m * DD + k : g_h[1] + m * DD + (k - DD);
        float4 v = __ldcg((const float4*)src);
        o[0] = v.x; o[1] = v.y; o[2] = v.z; o[3] = v.w;
    } else { // M_MABOUT
        const float* src = (k < DD) ? g_r[0] + m * DD + k : g_r[1] + m * DD + (k - DD);
        float2 v = __ldcg((const float2*)src);
        o[0] = v.x; o[1] = v.y;
    }
}

template <int MODE, int W>
__device__ __forceinline__ void loadB(const RP& P, int k, int n, int s, float* o) {
    const float* src;
    if constexpr (MODE == M_FRONT) {
        src = (s ? P.fc1_w : P.fc0_w) + (size_t)k * 256 + n;
    } else if constexpr (MODE == M_LSTHM) {
        const float* base = (k < DD) ? (s ? P.ltW : P.lvW)
                          : (k < 2 * DD) ? (s ? P.ltU : P.lvU)
                                         : (s ? P.ltV : P.lvV);
        src = base + (k & 255) * FOURD + n;
    } else if constexpr (MODE == M_ATT) {
        src = P.att_w + (size_t)k * K2D + n;
    } else if constexpr (MODE == M_RED) {
        src = (s ? P.red_t_w : P.red_v_w) + (size_t)k * 256 + n;
    } else {
        src = P.mab_w + (size_t)k * 256 + n;
    }
    if constexpr (W == 4) {
        float4 v = *(const float4*)src; o[0] = v.x; o[1] = v.y; o[2] = v.z; o[3] = v.w;
    } else {
        float2 v = *(const float2*)src; o[0] = v.x; o[1] = v.y;
    }
}

template <int MODE>
__device__ __forceinline__ const float* biasp(const RP& P, int s) {
    if constexpr (MODE == M_FRONT)      return s ? P.fc1_b : P.fc0_b;
    else if constexpr (MODE == M_LSTHM) return s ? P.ltb : P.lvb;
    else if constexpr (MODE == M_ATT)   return P.att_b;
    else if constexpr (MODE == M_RED)   return s ? P.red_t_b : P.red_v_b;
    else return P.mab_b;
}

template <int MODE>
__device__ __forceinline__ void storeC(int m, int n, int s, float v) {
    if constexpr (MODE == M_FRONT)       g_x[s][m * DD + n] = v;
    else if constexpr (MODE == M_LSTHM)  g_s[s][m * FOURD + n] = v;
    else if constexpr (MODE == M_ATT)    g_att[m * K2D + n] = v;
    else if constexpr (MODE == M_RED)    g_r[s][m * DD + n] = fmaxf(v, 0.0f);
    else                                 g_zz[m * DD + n] = v;
}

// ---------------- block-tile tf32 MMA GEMM (register-prefetch pipelined) ----
template <int MODE, int BM, int BN>
__device__ __forceinline__ void gemm_tile(const RP& P, int s, int m0, int n0, int t,
                                          float* As, float* Bs) {
    constexpr int KD = kdim<MODE>();
    constexpr int KT = 16;
    constexpr int SA = BM + 8, SB = BN + 8;
    constexpr int AW = (BM * KT) / 256, BW = (BN * KT) / 256;
    constexpr int WM = BM / 2, WN = BN / 4;
    constexpr int MT = WM / 16, NT = WN / 8;
    constexpr int TPRA = KT / AW;

    const int tid = threadIdx.x, lane = tid & 31, wid = tid >> 5;
    const int wm = (wid & 1) * WM, wn = (wid >> 1) * WN;
    const int grp = lane >> 2, thr = lane & 3;
    const int ar = tid / TPRA, ac = (tid % TPRA) * AW;
    const int br = tid >> 4, bc = (tid & 15) * BW;

    float ta[AW], tb[BW];
    loadA<MODE, AW>(P, m0 + ar, ac, s, t, ta);
    loadB<MODE, BW>(P, br, n0 + bc, s, tb);

    float acc[MT][NT][4] = {};

    for (int k0 = 0; k0 < KD; k0 += KT) {
#pragma unroll
        for (int w = 0; w < AW; w++) As[(ac + w) * SA + ar] = to_tf32(ta[w]);
#pragma unroll
        for (int w = 0; w < BW; w++) Bs[br * SB + bc + w] = to_tf32(tb[w]);
        __syncthreads();
        if (k0 + KT < KD) {
            loadA<MODE, AW>(P, m0 + ar, k0 + KT + ac, s, t, ta);
            loadB<MODE, BW>(P, k0 + KT + br, n0 + bc, s, tb);
        }
#pragma unroll
        for (int kk = 0; kk < KT; kk += 8) {
            float afr[MT][4], bfr[NT][2];
#pragma unroll
            for (int mt = 0; mt < MT; mt++) {
                int mb = wm + mt * 16;
                afr[mt][0] = As[(kk + thr) * SA + mb + grp];
                afr[mt][1] = As[(kk + thr) * SA + mb + grp + 8];
                afr[mt][2] = As[(kk + thr + 4) * SA + mb + grp];
                afr[mt][3] = As[(kk + thr + 4) * SA + mb + grp + 8];
            }
#pragma unroll
            for (int nt = 0; nt < NT; nt++) {
                int nb = wn + nt * 8;
                bfr[nt][0] = Bs[(kk + thr) * SB + nb + grp];
                bfr[nt][1] = Bs[(kk + thr + 4) * SB + nb + grp];
            }
#pragma unroll
            for (int mt = 0; mt < MT; mt++)
#pragma unroll
                for (int nt = 0; nt < NT; nt++)
                    mma_tf32(acc[mt][nt], afr[mt], bfr[nt]);
        }
        __syncthreads();
    }

    const float* bp = biasp<MODE>(P, s);
#pragma unroll
    for (int mt = 0; mt < MT; mt++)
#pragma unroll
        for (int nt = 0; nt < NT; nt++)
#pragma unroll
            for (int e = 0; e < 4; e++) {
                int m = m0 + wm + mt * 16 + grp + ((e >= 2) ? 8 : 0);
                int n = n0 + wn + nt * 8 + 2 * thr + (e & 1);
                storeC<MODE>(m, n, s, acc[mt][nt][e] + bp[n]);
            }
}

// ---------------- frontend kernel (separate launch; high occupancy) ---------
__global__ __launch_bounds__(256) void k_front(RP P) {
    __shared__ float As[16 * 72], Bs[16 * 72];
    gemm_tile<M_FRONT, 64, 64>(P, blockIdx.z, blockIdx.y * 64, blockIdx.x * 64, 0, As, Bs);
}

// ---------------- phase helpers ---------------------------------------------
__device__ __forceinline__ void phase_gates(int bid, int tid) {
#pragma unroll
    for (int j = 0; j < 4; j++) {
        int idx = bid * 1024 + j * 256 + tid;    // covers 2*BB*DD = 131072
        int s = idx >> 16;
        int r = idx & 65535;
        int b = r >> 8, d = r & 255;
        const float* sv = g_s[s] + b * FOURD;
        float f  = 1.0f / (1.0f + expf(-__ldcg(sv + d)));
        float ii = 1.0f / (1.0f + expf(-__ldcg(sv + DD + d)));
        float o  = 1.0f / (1.0f + expf(-__ldcg(sv + 2 * DD + d)));
        float ch = tanhf(__ldcg(sv + 3 * DD + d));
        float c  = f * g_c[s][r] + ii * ch;      // c: private to this block
        g_c[s][r] = c;
        g_h[s][r] = tanhf(c) * o;
    }
}

__device__ __forceinline__ void phase_softmax(int bid, int tid) {
    __shared__ float s1[8], s2[8];
    int lane = tid & 31, w = tid >> 5;
#pragma unroll 1
    for (int rr = 0; rr < 2; rr++) {
        float* row = g_att + (bid * 2 + rr) * K2D;
        float v[8];
        float lmax = -1e30f;
#pragma unroll
        for (int i = 0; i < 8; i++) { v[i] = __ldcg(row + tid + 256 * i); lmax = fmaxf(lmax, v[i]); }
#pragma unroll
        for (int o = 16; o; o >>= 1) lmax = fmaxf(lmax, __shfl_xor_sync(0xffffffffu, lmax, o));
        if (lane == 0) s1[w] = lmax;
        __syncthreads();
        float gmax = fmaxf(fmaxf(fmaxf(s1[0], s1[1]), fmaxf(s1[2], s1[3])),
                           fmaxf(fmaxf(s1[4], s1[5]), fmaxf(s1[6], s1[7])));
        float lsum = 0.0f;
#pragma unroll
        for (int i = 0; i < 8; i++) { v[i] = expf(v[i] - gmax); lsum += v[i]; }
#pragma unroll
        for (int o = 16; o; o >>= 1) lsum += __shfl_xor_sync(0xffffffffu, lsum, o);
        if (lane == 0) s2[w] = lsum;
        __syncthreads();
        float inv = 1.0f / (s2[0] + s2[1] + s2[2] + s2[3] + s2[4] + s2[5] + s2[6] + s2[7]);
#pragma unroll
        for (int i = 0; i < 8; i++) row[tid + 256 * i] = v[i] * inv;
        __syncthreads();
    }
}

__device__ __forceinline__ void phase_final(const RP& P, int bid, int tid, float* scr) {
    float* hrow = scr;          // 512 floats
    float* red  = scr + 512;    // 256 floats
#pragma unroll 1
    for (int rr = 0; rr < 2; rr++) {
        int b = bid * 2 + rr;
        hrow[tid]       = __ldcg(g_h[0] + b * DD + tid);
        hrow[256 + tid] = __ldcg(g_h[1] + b * DD + tid);
        __syncthreads();
        float acc = P.late0_b[tid];
#pragma unroll 8
        for (int k = 0; k < 512; k++) acc = fmaf(hrow[k], P.late0_w[k * DD + tid], acc);
        float w1a = P.late1_w[tid * 2 + 0], w1b = P.late1_w[tid * 2 + 1];

        red[tid] = acc * w1a;
        __syncthreads();
        for (int st = 128; st; st >>= 1) { if (tid < st) red[tid] += red[tid + st]; __syncthreads(); }
        if (tid == 0) P.out[b * 2 + 0] = red[0] + P.late1_b[0];
        __syncthreads();
        red[tid] = acc * w1b;
        __syncthreads();
        for (int st = 128; st; st >>= 1) { if (tid < st) red[tid] += red[tid + st]; __syncthreads(); }
        if (tid == 0) P.out[b * 2 + 1] = red[0] + P.late1_b[1];
        __syncthreads();
    }
}

// ---------------- persistent recurrence kernel ------------------------------
__global__ __launch_bounds__(256) void k_recur(RP P) {
    __shared__ float As[16 * 72], Bs[16 * 72];
    const int bid = blockIdx.x, tid = threadIdx.x;

    // init h, c, zz to zero
    for (int i = bid * 256 + tid; i < BB * DD; i += NBLK * 256) {
        g_h[0][i] = 0.f; g_h[1][i] = 0.f;
        g_c[0][i] = 0.f; g_c[1][i] = 0.f;
        g_zz[i] = 0.f;
    }
    gsync();

#pragma unroll 1
    for (int t = 0; t < TT; t++) {
        { // LSTHM pre-activations: 4m x 16n x 2s = 128 tiles of 64x64
            int s = bid >> 6, r = bid & 63;
            gemm_tile<M_LSTHM, 64, 64>(P, s, (r >> 4) * 64, (r & 15) * 64, t, As, Bs);
        }
        gsync();
        phase_gates(bid, tid);
        gsync();
        // ATT logits: 4m x 32n = 128 tiles of 64x64
        gemm_tile<M_ATT, 64, 64>(P, 0, (bid >> 5) * 64, (bid & 31) * 64, t, As, Bs);
        gsync();
        phase_softmax(bid, tid);
        gsync();
        { // fused attend + reduce + relu: 8m x 8n x 2s = 128 tiles of 32x32
            int s = bid >> 6, r = bid & 63;
            gemm_tile<M_RED, 32, 32>(P, s, (r >> 3) * 32, (r & 7) * 32, t, As, Bs);
        }
        gsync();
        // MAB out: 8m x 8n = 64 tiles of 32x32 (blocks >= 64 idle)
        if (bid < 64)
            gemm_tile<M_MABOUT, 32, 32>(P, 0, (bid >> 3) * 32, (bid & 7) * 32, t, As, Bs);
        gsync();
    }

    phase_final(P, bid, tid, As);
}

// ---------------- launch ----------------------------------------------------
extern "C" void kernel_launch(void* const* d_in, const int* in_sizes, int n_in,
                              void* d_out, int out_size) {
    RP P;
    P.xv      = (const float*)d_in[0];
    P.xt      = (const float*)d_in[1];
    P.fc0_w   = (const float*)d_in[2];
    P.fc0_b   = (const float*)d_in[3];
    P.fc1_w   = (const float*)d_in[4];
    P.fc1_b   = (const float*)d_in[5];
    P.lvW     = (const float*)d_in[6];
    P.lvU     = (const float*)d_in[7];
    P.lvV     = (const float*)d_in[8];
    P.lvb     = (const float*)d_in[9];
    P.ltW     = (const float*)d_in[10];
    P.ltU     = (const float*)d_in[11];
    P.ltV     = (const float*)d_in[12];
    P.ltb     = (const float*)d_in[13];
    P.att_w   = (const float*)d_in[14];
    P.att_b   = (const float*)d_in[15];
    P.red_v_w = (const float*)d_in[16];
    P.red_v_b = (const float*)d_in[17];
    P.red_t_w = (const float*)d_in[18];
    P.red_t_b = (const float*)d_in[19];
    P.mab_w   = (const float*)d_in[20];
    P.mab_b   = (const float*)d_in[21];
    P.late0_w = (const float*)d_in[22];
    P.late0_b = (const float*)d_in[23];
    P.late1_w = (const float*)d_in[24];
    P.late1_b = (const float*)d_in[25];
    P.out     = (float*)d_out;

    k_front<<<dim3(4, 100, 2), 256>>>(P);   // frontend GEMM, high occupancy
    k_recur<<<NBLK, 256>>>(P);              // persistent recurrence + head
}

// round 5
// speedup vs baseline: 2.2625x; 1.3810x over previous
#include <cuda_runtime.h>
#include <cstdint>

#define BB 256
#define TT 25
#define PRE 2048
#define DD 256
#define K2D 2048
#define NBLK 128
#define STAGES 4

// ---------------- scratch (device globals) ----------------------------------
__device__ float g_x[2][BB * TT * DD];
__device__ float g_h[2][BB * DD];
__device__ float g_c[2][BB * DD];
__device__ float g_zz[BB * DD];
__device__ float g_att[BB * K2D];
__device__ float g_ad[2][BB * 1024];   // attended att*h -> RED A operand
__device__ float g_r[2][BB * DD];

// two-level grid barrier state (self-resetting)
__device__ unsigned g_leaf[16 * 32];
__device__ unsigned g_root = 0;
__device__ unsigned g_gen = 0;

struct RP {
    const float *xv, *xt, *fc0_w, *fc0_b, *fc1_w, *fc1_b;
    const float *lvW, *lvU, *lvV, *lvb, *ltW, *ltU, *ltV, *ltb;
    const float *att_w, *att_b, *red_v_w, *red_v_b, *red_t_w, *red_t_b, *mab_w, *mab_b;
    const float *late0_w, *late0_b, *late1_w, *late1_b;
    float* out;
};

enum { M_FRONT = 0, M_LSTHM, M_ATT, M_RED, M_MABOUT };

template <int MODE> __host__ __device__ constexpr int kdim() {
    return MODE == M_FRONT ? 2048 : MODE == M_LSTHM ? 768
         : MODE == M_ATT   ? 512  : MODE == M_RED   ? 1024 : 512;
}

// ---------------- grid sync (two-level, L2-atomic) ---------------------------
__device__ __forceinline__ void gsync() {
    __threadfence();
    __syncthreads();
    if (threadIdx.x == 0) {
        unsigned gen = *(volatile unsigned*)&g_gen;
        unsigned li = (blockIdx.x & 15) * 32;
        if (atomicAdd(&g_leaf[li], 1u) == 7u) {        // 8 blocks per leaf
            g_leaf[li] = 0;
            __threadfence();
            if (atomicAdd(&g_root, 1u) == 15u) {       // 16 leaves
                g_root = 0;
                __threadfence();
                *(volatile unsigned*)&g_gen = gen + 1;
            } else {
                while (*(volatile unsigned*)&g_gen == gen) {}
            }
        } else {
            while (*(volatile unsigned*)&g_gen == gen) {}
        }
    }
    __syncthreads();
}

// ---------------- cp.async / tf32 helpers ------------------------------------
__device__ __forceinline__ void cp16(uint32_t dst, const void* src) {
    asm volatile("cp.async.cg.shared.global [%0], [%1], 16;" :: "r"(dst), "l"(src));
}
__device__ __forceinline__ void cp4(uint32_t dst, const void* src) {
    asm volatile("cp.async.ca.shared.global [%0], [%1], 4;" :: "r"(dst), "l"(src));
}
__device__ __forceinline__ void cpcommit() { asm volatile("cp.async.commit_group;"); }
__device__ __forceinline__ void cpwait()   { asm volatile("cp.async.wait_group %0;" :: "n"(STAGES - 1)); }

__device__ __forceinline__ float to_tf32(float x) {
    asm("cvt.rna.tf32.f32 %0, %0;" : "+f"(x));
    return x;
}
__device__ __forceinline__ float sigm(float x) { return 1.0f / (1.0f + expf(-x)); }

__device__ __forceinline__ void mma_tf32(float* acc, const float* a, const float* b) {
    asm volatile(
        "mma.sync.aligned.m16n8k8.row.col.f32.tf32.tf32.f32 "
        "{%0,%1,%2,%3}, {%4,%5,%6,%7}, {%8,%9}, {%0,%1,%2,%3};\n"
        : "+f"(acc[0]), "+f"(acc[1]), "+f"(acc[2]), "+f"(acc[3])
        : "r"(__float_as_uint(a[0])), "r"(__float_as_uint(a[1])),
          "r"(__float_as_uint(a[2])), "r"(__float_as_uint(a[3])),
          "r"(__float_as_uint(b[0])), "r"(__float_as_uint(b[1])));
}

// ---------------- A-row pointer (k contiguous) -------------------------------
template <int MODE>
__device__ __forceinline__ const float* rowA(const RP& P, int m, int k, int s, int t) {
    if constexpr (MODE == M_FRONT)  return (s ? P.xt : P.xv) + (size_t)m * PRE + k;
    else if constexpr (MODE == M_LSTHM) {
        if (k < DD)          return g_x[s] + (m * TT + t) * DD + k;
        else if (k < 2 * DD) return g_h[s] + m * DD + (k - DD);
        else                 return g_zz + m * DD + (k - 2 * DD);
    } else if constexpr (MODE == M_ATT) {
        return (k < DD) ? g_h[0] + m * DD + k : g_h[1] + m * DD + (k - DD);
    } else if constexpr (MODE == M_RED) {
        return g_ad[s] + m * 1024 + k;
    } else {
        return (k < DD) ? g_r[0] + m * DD + k : g_r[1] + m * DD + (k - DD);
    }
}

// ---------------- pipelined tf32 MMA GEMM ------------------------------------
// smem strides: As[m][k] stride 20 floats; Bs[k][n] stride 72 floats.
template <int MODE, int BM, int BN>
__device__ __forceinline__ void gemm_pipe(const RP& P, int s, int m0, int n0, int t,
                                          float* smA, float* smB, float* smG,
                                          uint32_t saA, uint32_t saB) {
    constexpr int KD = kdim<MODE>();
    constexpr int NITER = KD / 16;
    constexpr int ABUF = BM * 20;        // floats per A stage
    constexpr int BBUF = 16 * 72;        // floats per B stage
    constexpr int WM = BM / 2, WN = BN / 4;
    constexpr int MT = WM / 16, NT = WN / 8;

    const int tid = threadIdx.x, lane = tid & 31, wid = tid >> 5;
    const int wm = (wid & 1) * WM, wn = (wid >> 1) * WN;
    const int grp = lane >> 2, thr = lane & 3;

    float acc[MT][NT][4] = {};

    // ---- issue one k-tile into stage buffer ----
    auto issue = [&](int i) {
        if (i < NITER) {
            int buf = i & (STAGES - 1);
            int k0 = i * 16;
            uint32_t aA = saA + buf * ABUF * 4;
            uint32_t aB = saB + buf * BBUF * 4;
            if (tid < BM * 4) {
                int m = tid >> 2, kq = (tid & 3) * 4;
                cp16(aA + (m * 20 + kq) * 4, rowA<MODE>(P, m0 + m, k0 + kq, s, t));
            }
            if constexpr (MODE == M_LSTHM) {
                // interleaved gate columns: packed n -> actual (n&3)*256 + (n>>2)
                int k = tid >> 4, c4 = (tid & 15) * 4;
                int kg = k0 + k;
                const float* base = (kg < DD) ? (s ? P.ltW : P.lvW)
                                  : (kg < 2 * DD) ? (s ? P.ltU : P.lvU)
                                                  : (s ? P.ltV : P.lvV);
                const float* row = base + (size_t)(kg & 255) * 1024;
#pragma unroll
                for (int j = 0; j < 4; j++) {
                    int n = n0 + c4 + j;
                    int a = (n & 3) * 256 + (n >> 2);
                    cp4(aB + (k * 72 + c4 + j) * 4, row + a);
                }
            } else {
                const float* row;
                int k, n4;
                if constexpr (BN == 64) { k = tid >> 4; n4 = (tid & 15) * 4; }
                else                    { k = tid >> 3; n4 = (tid & 7) * 4; }
                bool act = (BN == 64) || (tid < 128);
                if (act) {
                    int kg = k0 + k;
                    if constexpr (MODE == M_FRONT)      row = (s ? P.fc1_w : P.fc0_w) + (size_t)kg * 256;
                    else if constexpr (MODE == M_ATT)   row = P.att_w + (size_t)kg * K2D;
                    else if constexpr (MODE == M_RED)   row = (s ? P.red_t_w : P.red_v_w) + (size_t)kg * 256;
                    else                                row = P.mab_w + (size_t)kg * 256;
                    cp16(aB + (k * 72 + n4) * 4, row + n0 + n4);
                }
            }
        }
        cpcommit();
    };

#pragma unroll
    for (int i = 0; i < STAGES - 1; i++) issue(i);

    for (int i = 0; i < NITER; i++) {
        issue(i + STAGES - 1);
        cpwait();
        __syncthreads();
        const float* As = smA + (i & (STAGES - 1)) * ABUF;
        const float* Bs = smB + (i & (STAGES - 1)) * BBUF;
#pragma unroll
        for (int kk = 0; kk < 16; kk += 8) {
            float afr[MT][4], bfr[NT][2];
#pragma unroll
            for (int mt = 0; mt < MT; mt++) {
                int mb = wm + mt * 16;
                afr[mt][0] = to_tf32(As[(mb + grp) * 20 + kk + thr]);
                afr[mt][1] = to_tf32(As[(mb + grp + 8) * 20 + kk + thr]);
                afr[mt][2] = to_tf32(As[(mb + grp) * 20 + kk + thr + 4]);
                afr[mt][3] = to_tf32(As[(mb + grp + 8) * 20 + kk + thr + 4]);
            }
#pragma unroll
            for (int nt = 0; nt < NT; nt++) {
                int nb = wn + nt * 8;
                bfr[nt][0] = to_tf32(Bs[(kk + thr) * 72 + nb + grp]);
                bfr[nt][1] = to_tf32(Bs[(kk + thr + 4) * 72 + nb + grp]);
            }
#pragma unroll
            for (int mt = 0; mt < MT; mt++)
#pragma unroll
                for (int nt = 0; nt < NT; nt++)
                    mma_tf32(acc[mt][nt], afr[mt], bfr[nt]);
        }
        __syncthreads();
    }

    // ---- epilogue ----
    if constexpr (MODE == M_LSTHM) {
        const float* bp = s ? P.ltb : P.lvb;
#pragma unroll
        for (int mt = 0; mt < MT; mt++)
#pragma unroll
            for (int nt = 0; nt < NT; nt++)
#pragma unroll
                for (int e = 0; e < 4; e++) {
                    int m_l = wm + mt * 16 + grp + ((e >= 2) ? 8 : 0);
                    int n_l = wn + nt * 8 + 2 * thr + (e & 1);
                    int np = n0 + n_l;
                    int a = (np & 3) * 256 + (np >> 2);
                    smG[m_l * 68 + n_l] = acc[mt][nt][e] + bp[a];
                }
        __syncthreads();
#pragma unroll
        for (int j = 0; j < 4; j++) {
            int p = tid + 256 * j;
            int m_l = p & 63, dl = p >> 6;
            float4 gv = *(const float4*)&smG[m_l * 68 + dl * 4];  // f,i,o,ch
            int m = m0 + m_l, d = (n0 >> 2) + dl;
            float f = sigm(gv.x), ii = sigm(gv.y), oo = sigm(gv.z), ch = tanhf(gv.w);
            float c = f * g_c[s][m * DD + d] + ii * ch;
            g_c[s][m * DD + d] = c;
            g_h[s][m * DD + d] = tanhf(c) * oo;
        }
        __syncthreads();
    } else {
        const float* bp;
        if constexpr (MODE == M_FRONT)    bp = s ? P.fc1_b : P.fc0_b;
        else if constexpr (MODE == M_ATT) bp = P.att_b;
        else if constexpr (MODE == M_RED) bp = s ? P.red_t_b : P.red_v_b;
        else                              bp = P.mab_b;
#pragma unroll
        for (int mt = 0; mt < MT; mt++)
#pragma unroll
            for (int nt = 0; nt < NT; nt++)
#pragma unroll
                for (int e = 0; e < 4; e++) {
                    int m = m0 + wm + mt * 16 + grp + ((e >= 2) ? 8 : 0);
                    int n = n0 + wn + nt * 8 + 2 * thr + (e & 1);
                    float v = acc[mt][nt][e] + bp[n];
                    if constexpr (MODE == M_FRONT)     g_x[s][m * DD + n] = v;
                    else if constexpr (MODE == M_ATT)  g_att[m * K2D + n] = v;
                    else if constexpr (MODE == M_RED)  g_r[s][m * DD + n] = fmaxf(v, 0.0f);
                    else                               g_zz[m * DD + n] = v;
                }
    }
}

// ---------------- softmax + attd precompute ----------------------------------
__device__ __forceinline__ void phase_softmax(const RP& P, int bid, int tid, float* hsm) {
    __shared__ float s1[8], s2[8];
    int lane = tid & 31, w = tid >> 5;
#pragma unroll 1
    for (int rr = 0; rr < 2; rr++) {
        int m = bid * 2 + rr;
        hsm[tid]       = __ldcg(g_h[0] + m * DD + tid);
        hsm[256 + tid] = __ldcg(g_h[1] + m * DD + tid);
        __syncthreads();
        const float* row = g_att + m * K2D;
        float v[8];
        float lmax = -1e30f;
#pragma unroll
        for (int i = 0; i < 8; i++) { v[i] = __ldcg(row + tid + 256 * i); lmax = fmaxf(lmax, v[i]); }
#pragma unroll
        for (int o = 16; o; o >>= 1) lmax = fmaxf(lmax, __shfl_xor_sync(0xffffffffu, lmax, o));
        if (lane == 0) s1[w] = lmax;
        __syncthreads();
        float gmax = fmaxf(fmaxf(fmaxf(s1[0], s1[1]), fmaxf(s1[2], s1[3])),
                           fmaxf(fmaxf(s1[4], s1[5]), fmaxf(s1[6], s1[7])));
        float lsum = 0.0f;
#pragma unroll
        for (int i = 0; i < 8; i++) { v[i] = expf(v[i] - gmax); lsum += v[i]; }
#pragma unroll
        for (int o = 16; o; o >>= 1) lsum += __shfl_xor_sync(0xffffffffu, lsum, o);
        if (lane == 0) s2[w] = lsum;
        __syncthreads();
        float inv = 1.0f / (s2[0] + s2[1] + s2[2] + s2[3] + s2[4] + s2[5] + s2[6] + s2[7]);
#pragma unroll
        for (int i = 0; i < 8; i++) {
            int c = tid + 256 * i;
            int slot = c >> 9, sx = (c >> 8) & 1, d = c & 255;
            g_ad[sx][m * 1024 + slot * 256 + d] = v[i] * inv * hsm[sx * 256 + d];
        }
        __syncthreads();
    }
}

// ---------------- final head -------------------------------------------------
__device__ __forceinline__ void phase_final(const RP& P, int bid, int tid, float* scr) {
    float* hrow = scr;
    float* red  = scr + 512;
#pragma unroll 1
    for (int rr = 0; rr < 2; rr++) {
        int b = bid * 2 + rr;
        hrow[tid]       = __ldcg(g_h[0] + b * DD + tid);
        hrow[256 + tid] = __ldcg(g_h[1] + b * DD + tid);
        __syncthreads();
        float acc = P.late0_b[tid];
#pragma unroll 8
        for (int k = 0; k < 512; k++) acc = fmaf(hrow[k], P.late0_w[k * DD + tid], acc);
        float w1a = P.late1_w[tid * 2 + 0], w1b = P.late1_w[tid * 2 + 1];

        red[tid] = acc * w1a;
        __syncthreads();
        for (int st = 128; st; st >>= 1) { if (tid < st) red[tid] += red[tid + st]; __syncthreads(); }
        if (tid == 0) P.out[b * 2 + 0] = red[0] + P.late1_b[0];
        __syncthreads();
        red[tid] = acc * w1b;
        __syncthreads();
        for (int st = 128; st; st >>= 1) { if (tid < st) red[tid] += red[tid + st]; __syncthreads(); }
        if (tid == 0) P.out[b * 2 + 1] = red[0] + P.late1_b[1];
        __syncthreads();
    }
}

// ---------------- frontend kernel --------------------------------------------
__global__ __launch_bounds__(256) void k_front(RP P) {
    __shared__ float smA[STAGES * 64 * 20];
    __shared__ float smB[STAGES * 16 * 72];
    __shared__ float smG[64 * 68];
    uint32_t saA = (uint32_t)__cvta_generic_to_shared(smA);
    uint32_t saB = (uint32_t)__cvta_generic_to_shared(smB);
    gemm_pipe<M_FRONT, 64, 64>(P, blockIdx.z, blockIdx.y * 64, blockIdx.x * 64, 0,
                               smA, smB, smG, saA, saB);
}

// ---------------- persistent recurrence kernel -------------------------------
__global__ __launch_bounds__(256) void k_recur(RP P) {
    __shared__ float smA[STAGES * 64 * 20];
    __shared__ float smB[STAGES * 16 * 72];
    __shared__ float smG[64 * 68];
    uint32_t saA = (uint32_t)__cvta_generic_to_shared(smA);
    uint32_t saB = (uint32_t)__cvta_generic_to_shared(smB);
    const int bid = blockIdx.x, tid = threadIdx.x;

    for (int i = bid * 256 + tid; i < BB * DD; i += NBLK * 256) {
        g_h[0][i] = 0.f; g_h[1][i] = 0.f;
        g_c[0][i] = 0.f; g_c[1][i] = 0.f;
        g_zz[i] = 0.f;
    }
    gsync();

#pragma unroll 1
    for (int t = 0; t < TT; t++) {
        { // LSTHM + fused gates: 2s x 4m x 16n(packed) tiles of 64x64
            int s = bid >> 6, r = bid & 63;
            gemm_pipe<M_LSTHM, 64, 64>(P, s, (r >> 4) * 64, (r & 15) * 64, t,
                                       smA, smB, smG, saA, saB);
        }
        gsync();
        // ATT logits: 4m x 32n tiles of 64x64
        gemm_pipe<M_ATT, 64, 64>(P, 0, (bid >> 5) * 64, (bid & 31) * 64, t,
                                 smA, smB, smG, saA, saB);
        gsync();
        phase_softmax(P, bid, tid, smG);
        gsync();
        { // attended reduce + relu: 2s x 8m x 8n tiles of 32x32
            int s = bid >> 6, r = bid & 63;
            gemm_pipe<M_RED, 32, 32>(P, s, (r >> 3) * 32, (r & 7) * 32, t,
                                     smA, smB, smG, saA, saB);
        }
        gsync();
        // MAB out: 8m x 8n tiles of 32x32 (64 blocks)
        if (bid < 64)
            gemm_pipe<M_MABOUT, 32, 32>(P, 0, (bid >> 3) * 32, (bid & 7) * 32, t,
                                        smA, smB, smG, saA, saB);
        gsync();
    }

    phase_final(P, bid, tid, smG);
}

// ---------------- launch -----------------------------------------------------
extern "C" void kernel_launch(void* const* d_in, const int* in_sizes, int n_in,
                              void* d_out, int out_size) {
    RP P;
    P.xv      = (const float*)d_in[0];
    P.xt      = (const float*)d_in[1];
    P.fc0_w   = (const float*)d_in[2];
    P.fc0_b   = (const float*)d_in[3];
    P.fc1_w   = (const float*)d_in[4];
    P.fc1_b   = (const float*)d_in[5];
    P.lvW     = (const float*)d_in[6];
    P.lvU     = (const float*)d_in[7];
    P.lvV     = (const float*)d_in[8];
    P.lvb     = (const float*)d_in[9];
    P.ltW     = (const float*)d_in[10];
    P.ltU     = (const float*)d_in[11];
    P.ltV     = (const float*)d_in[12];
    P.ltb     = (const float*)d_in[13];
    P.att_w   = (const float*)d_in[14];
    P.att_b   = (const float*)d_in[15];
    P.red_v_w = (const float*)d_in[16];
    P.red_v_b = (const float*)d_in[17];
    P.red_t_w = (const float*)d_in[18];
    P.red_t_b = (const float*)d_in[19];
    P.mab_w   = (const float*)d_in[20];
    P.mab_b   = (const float*)d_in[21];
    P.late0_w = (const float*)d_in[22];
    P.late0_b = (const float*)d_in[23];
    P.late1_w = (const float*)d_in[24];
    P.late1_b = (const float*)d_in[25];
    P.out     = (float*)d_out;

    k_front<<<dim3(4, 100, 2), 256>>>(P);
    k_recur<<<NBLK, 256>>>(P);
}